// round 11
// baseline (speedup 1.0000x reference)
#include <cuda_runtime.h>
#include <cuda_fp16.h>
#include <math.h>

#define BNUM 1024
#define TT   48
#define NT   47
#define RNNV 64
#define GG   256
#define NOBJ 25
#define HID  32
#define V1   2001
#define NROW (NT*BNUM)

__device__ float g_xproj[(size_t)NROW*GG];
__device__ float g_hist[(size_t)NROW*RNNV];
__device__ float g_pre1[BNUM*NOBJ*HID];
__device__ float g_pre2[BNUM*NOBJ*HID];
__device__ float g_diff[BNUM*NOBJ*4];
__device__ float g_WAx[RNNV*GG];
// fp32 gate weights, 5 matrices (WAl,WAh,WLa,WLh,WLl), packed k-pairs:
// float index = m*16384 + (k>>1)*512 + g*2 + (k&1)
__device__ __align__(16) float g_WP[5*16384];
// fp16 output weights: [k][2016] (cols >= 2001 zero-padded)
__device__ __align__(16) __half g_fcwh[RNNV*2016];

typedef unsigned long long u64;

__device__ __forceinline__ u64 pack2(float lo, float hi){
    u64 r; asm("mov.b64 %0, {%1, %2};" : "=l"(r) : "f"(lo), "f"(hi)); return r;
}
__device__ __forceinline__ u64 dup2(float x){ return pack2(x, x); }
__device__ __forceinline__ void fma2(u64& acc, u64 a, u64 b){
    asm("fma.rn.f32x2 %0, %1, %2, %0;" : "+l"(acc) : "l"(a), "l"(b));
}
__device__ __forceinline__ float2 unpack2(u64 v){
    float2 f; asm("mov.b64 {%0, %1}, %2;" : "=f"(f.x), "=f"(f.y) : "l"(v)); return f;
}
__device__ __forceinline__ float sigf(float x){
    return __fdividef(1.0f, 1.0f + __expf(-x));
}
__device__ __forceinline__ float ftanh(float x){
    float e = __expf(-2.0f*x);
    return __fdividef(1.0f - e, 1.0f + e);
}

// ------------------------------------------------------------------
__global__ void prep_weights_kernel(const float* __restrict__ WihA, const float* __restrict__ WhhA,
                                    const float* __restrict__ WihL, const float* __restrict__ WhhL,
                                    const float* __restrict__ fcw)
{
    int i = blockIdx.x*blockDim.x + threadIdx.x;
    if (i < RNNV*GG){
        int k = i / GG, g = i % GG;
        g_WAx[i] = WihA[g*128 + 64 + k];
    }
    if (i < 5*RNNV*GG){
        int m = i / 16384, rem = i % 16384;
        int k = rem >> 8, g = rem & 255;
        float w;
        if      (m == 0) w = WihA[g*128 + k];
        else if (m == 1) w = WhhA[g*64 + k];
        else if (m == 2) w = WihL[g*128 + k];
        else if (m == 3) w = WihL[g*128 + 64 + k];
        else             w = WhhL[g*64 + k];
        g_WP[m*16384 + (k>>1)*512 + g*2 + (k&1)] = w;
    }
    if (i < RNNV*V1){
        int k = i / V1, v = i % V1;
        g_fcwh[k*2016 + v] = __float2half(fcw[v*RNNV + k]);
    }
    if (i < RNNV*15){
        int k = i / 15, v = V1 + i % 15;
        g_fcwh[k*2016 + v] = __float2half(0.0f);
    }
}

// ------------------------------------------------------------------
__global__ void prep_canvas_kernel(const float* __restrict__ prev, const float* __restrict__ finalc,
                                   const float* __restrict__ a1w1, const float* __restrict__ a1b1,
                                   const float* __restrict__ a2w1, const float* __restrict__ a2b1)
{
    int i = blockIdx.x*blockDim.x + threadIdx.x;
    if (i >= BNUM*NOBJ*HID) return;
    int j = i & 31, bn = i >> 5;
    float p0 = prev[bn*4+0], p1 = prev[bn*4+1], p2 = prev[bn*4+2], p3 = prev[bn*4+3];
    bool masked = (p0+p1+p2+p3) > 0.0f;
    float d0 = masked ? -1.0f : finalc[bn*4+0];
    float d1 = masked ? -1.0f : finalc[bn*4+1];
    float d2 = masked ? -1.0f : finalc[bn*4+2];
    float d3 = masked ? -1.0f : finalc[bn*4+3];
    const float* w1 = a1w1 + j*68 + 64;
    const float* w2 = a2w1 + j*68 + 64;
    g_pre1[i] = a1b1[j] + d0*w1[0] + d1*w1[1] + d2*w1[2] + d3*w1[3];
    g_pre2[i] = a2b1[j] + p0*w2[0] + p1*w2[1] + p2*w2[2] + p3*w2[3];
    if (j == 0){
        g_diff[bn*4+0] = d0; g_diff[bn*4+1] = d1;
        g_diff[bn*4+2] = d2; g_diff[bn*4+3] = d3;
    }
}

// ------------------------------------------------------------------
__global__ __launch_bounds__(256) void xproj_kernel(
    const int* __restrict__ inst, const float* __restrict__ embed,
    const float* __restrict__ b_ih, const float* __restrict__ b_hh)
{
    __shared__ __align__(16) float se[RNNV*16];  // [k][r]
    const int tid = threadIdx.x;
    const int m0 = blockIdx.x * 16;
    for (int i = tid; i < 16*RNNV; i += 256){
        int r = i >> 6, k = i & 63;
        int m = m0 + r;
        int t = m >> 10, b = m & 1023;
        int tok = inst[b*TT + t];
        se[k*16 + r] = embed[tok*RNNV + k];
    }
    __syncthreads();
    const int g = tid;
    float bias = b_ih[g] + b_hh[g];
    u64 acc[8];
    #pragma unroll
    for (int p = 0; p < 8; ++p) acc[p] = dup2(bias);
    const float* w = g_WAx + g;
    #pragma unroll 8
    for (int k = 0; k < RNNV; ++k){
        u64 wd = dup2(w[k*GG]);
        const float* e = se + k*16;
        ulonglong2 e0 = *(const ulonglong2*)(e);
        ulonglong2 e1 = *(const ulonglong2*)(e + 4);
        ulonglong2 e2 = *(const ulonglong2*)(e + 8);
        ulonglong2 e3 = *(const ulonglong2*)(e + 12);
        fma2(acc[0], wd, e0.x); fma2(acc[1], wd, e0.y);
        fma2(acc[2], wd, e1.x); fma2(acc[3], wd, e1.y);
        fma2(acc[4], wd, e2.x); fma2(acc[5], wd, e2.y);
        fma2(acc[6], wd, e3.x); fma2(acc[7], wd, e3.y);
    }
    float* xp = g_xproj + (size_t)m0*GG + g;
    #pragma unroll
    for (int p = 0; p < 8; ++p){
        float2 f = unpack2(acc[p]);
        xp[(size_t)(2*p)*GG]   = f.x;
        xp[(size_t)(2*p+1)*GG] = f.y;
    }
}

// ------------------------------------------------------------------
// recurrent: 8 rows/CTA, 512 threads, 128 CTAs
// ALL gate weights (attention + language) live in REGISTERS
#define R_HL    0        // 512  [k][8]
#define R_HA    512      // 512
#define R_AV    1024     // 512
#define R_HAR   1536     // 512  [r][64]
#define R_CA    2048     // 512  [r][u]
#define R_CL    2560     // 512
#define R_PART  3072     // 4096 [hf][r][g]
#define R_PRE   7168     // 14400 [a*7200 + r*900 + n*36 + j]
#define R_W1H   21568    // 4352  [a*2176 + j*68 + k]
#define R_TW2T  25920    // 2304  [u*36 + j]
#define R_MEM   28224    // 1600  [a][r][n*4+d]
#define R_HP    29824    // 512   [r][64]
#define R_AO    30336    // 64    [r][8]
#define R_T1    30400    // 256   [r][32]
#define R_TW1T  30656    // 256   [d][j]
#define R_W2A   30912    // 64    [a][j]
#define R_TB1   30976    // 32
#define R_TB2   31008    // 64
#define R_BL    31072    // 256
#define R_B2A   31328    // 2
#define R_TOTAL 31336

__global__ __launch_bounds__(512) void recurrent_kernel(
    const float* __restrict__ a1w1, const float* __restrict__ a1w2, const float* __restrict__ a1b2,
    const float* __restrict__ a2w1, const float* __restrict__ a2w2, const float* __restrict__ a2b2,
    const float* __restrict__ tw1,  const float* __restrict__ tb1,
    const float* __restrict__ tw2,  const float* __restrict__ tb2,
    const float* __restrict__ bihl, const float* __restrict__ bhhl,
    const float* __restrict__ prev)
{
    extern __shared__ __align__(16) float sm[];
    const int tid  = threadIdx.x;
    const int row0 = blockIdx.x * 8;

    // ------- one-time init -------
    for (int i = tid; i < 3072; i += 512) sm[i] = 0.f;   // HL HA AV HAR CA CL
    for (int i = tid; i < 12800; i += 512){
        int a = i / 6400, rem = i % 6400;
        int r = rem / 800, rem2 = rem % 800;
        int n = rem2 >> 5, j = rem2 & 31;
        const float* src = a ? g_pre2 : g_pre1;
        sm[R_PRE + a*7200 + r*900 + n*36 + j] = src[((size_t)(row0+r)*NOBJ + n)*HID + j];
    }
    for (int i = tid; i < 4096; i += 512){
        int a = i >> 11, j = (i >> 6) & 31, k = i & 63;
        sm[R_W1H + a*2176 + j*68 + k] = (a ? a2w1 : a1w1)[j*68 + k];
    }
    for (int i = tid; i < 2048; i += 512){
        int u = i >> 5, j = i & 31;
        sm[R_TW2T + u*36 + j] = tw2[u*HID + j];
    }
    for (int i = tid; i < 1600; i += 512){
        int a = i / 800, rem = i % 800, r = rem / 100, q = rem % 100;
        sm[R_MEM + i] = a ? prev[(row0+r)*100 + q] : g_diff[(row0+r)*100 + q];
    }
    if (tid < 256){ int j = tid >> 3, d = tid & 7; sm[R_TW1T + d*32 + j] = tw1[j*8 + d]; }
    if (tid < 32){
        sm[R_W2A + tid]      = a1w2[tid];
        sm[R_W2A + 32 + tid] = a2w2[tid];
        sm[R_TB1 + tid]      = tb1[tid];
    }
    if (tid < 64)  sm[R_TB2 + tid] = tb2[tid];
    if (tid < 256) sm[R_BL + tid]  = bihl[tid] + bhhl[tid];
    if (tid < 2)   sm[R_B2A + tid] = tid ? a2b2[0] : a1b2[0];
    __syncthreads();

    const int g    = tid & 255;
    const int hf   = tid >> 8;
    const int k0   = hf << 5;
    const int wid  = tid >> 5;
    const int lane = tid & 31;
    const int cu   = tid & 63, cr = tid >> 6;

    const int kp0 = k0 >> 1;
    const float2* wAl = (const float2*)(g_WP + 0*16384) + kp0*256 + g;
    const float2* wAh = (const float2*)(g_WP + 1*16384) + kp0*256 + g;
    const float2* wLa = (const float2*)(g_WP + 2*16384) + kp0*256 + g;
    const float2* wLh = (const float2*)(g_WP + 3*16384) + kp0*256 + g;
    const float2* wLl = (const float2*)(g_WP + 4*16384) + kp0*256 + g;

    // ---- preload ALL gate weights into registers (t-invariant) ----
    float2 rAl[16], rAh[16], rLa[16], rLh[16], rLl[16];
    #pragma unroll
    for (int i = 0; i < 16; ++i){
        rAl[i] = wAl[i*256]; rAh[i] = wAh[i*256];
        rLa[i] = wLa[i*256]; rLh[i] = wLh[i*256]; rLl[i] = wLl[i*256];
    }

    for (int t = 0; t < NT; ++t){
        // ==== phase 1: attention-LSTM gates (split-k, weights in regs) ====
        {
            float x0,x1,x2,x3,x4,x5,x6,x7;
            if (hf == 0){
                const float* xp = g_xproj + ((size_t)t*BNUM + row0)*GG + g;
                x0=xp[0];    x1=xp[GG];   x2=xp[2*GG]; x3=xp[3*GG];
                x4=xp[4*GG]; x5=xp[5*GG]; x6=xp[6*GG]; x7=xp[7*GG];
            } else { x0=x1=x2=x3=x4=x5=x6=x7=0.f; }
            u64 a0=0ull, a1=0ull, a2=0ull, a3=0ull;
            #pragma unroll
            for (int i = 0; i < 16; ++i){
                const float* hl = sm + R_HL + (k0 + 2*i)*8;
                const float* ha = sm + R_HA + (k0 + 2*i)*8;
                ulonglong2 l0 = *(const ulonglong2*)(hl);
                ulonglong2 l1 = *(const ulonglong2*)(hl + 4);
                ulonglong2 l2 = *(const ulonglong2*)(hl + 8);
                ulonglong2 l3 = *(const ulonglong2*)(hl + 12);
                ulonglong2 b0 = *(const ulonglong2*)(ha);
                ulonglong2 b1 = *(const ulonglong2*)(ha + 4);
                ulonglong2 b2 = *(const ulonglong2*)(ha + 8);
                ulonglong2 b3 = *(const ulonglong2*)(ha + 12);
                u64 wl0 = dup2(rAl[i].x), wl1 = dup2(rAl[i].y);
                u64 wh0 = dup2(rAh[i].x), wh1 = dup2(rAh[i].y);
                fma2(a0,wl0,l0.x); fma2(a1,wl0,l0.y); fma2(a2,wl0,l1.x); fma2(a3,wl0,l1.y);
                fma2(a0,wh0,b0.x); fma2(a1,wh0,b0.y); fma2(a2,wh0,b1.x); fma2(a3,wh0,b1.y);
                fma2(a0,wl1,l2.x); fma2(a1,wl1,l2.y); fma2(a2,wl1,l3.x); fma2(a3,wl1,l3.y);
                fma2(a0,wh1,b2.x); fma2(a1,wh1,b2.y); fma2(a2,wh1,b3.x); fma2(a3,wh1,b3.y);
            }
            float* pp = sm + R_PART + hf*2048 + g;
            float2 f;
            f = unpack2(a0); pp[0]=f.x+x0;    pp[256]=f.y+x1;
            f = unpack2(a1); pp[512]=f.x+x2;  pp[768]=f.y+x3;
            f = unpack2(a2); pp[1024]=f.x+x4; pp[1280]=f.y+x5;
            f = unpack2(a3); pp[1536]=f.x+x6; pp[1792]=f.y+x7;
        }
        __syncthreads();
        // ==== phase 2+3: attention cell + hp, warp-per-row ====
        if (wid < 8){
            const int r = wid;
            #pragma unroll
            for (int h = 0; h < 2; ++h){
                int u = lane + h*32;
                const float* p = sm + R_PART + r*256 + u;
                float gi = p[0]   + p[2048];
                float gf = p[64]  + p[2112];
                float gg = p[128] + p[2176];
                float go = p[192] + p[2240];
                float c = sigf(gf)*sm[R_CA + r*64 + u] + sigf(gi)*ftanh(gg);
                sm[R_CA + r*64 + u] = c;
                float hv = sigf(go)*ftanh(c);
                sm[R_HA + u*8 + r]   = hv;
                sm[R_HAR + r*64 + u] = hv;
            }
            __syncwarp();
            const float4* hv4 = (const float4*)(sm + R_HAR + r*64);
            const float4* w0v = (const float4*)(sm + R_W1H + lane*68);
            const float4* w1v = (const float4*)(sm + R_W1H + 2176 + lane*68);
            float acc0 = 0.f, acc1 = 0.f;
            #pragma unroll
            for (int q = 0; q < 16; ++q){
                float4 h4 = hv4[q], wa = w0v[q], wb = w1v[q];
                acc0 += h4.x*wa.x + h4.y*wa.y + h4.z*wa.z + h4.w*wa.w;
                acc1 += h4.x*wb.x + h4.y*wb.y + h4.z*wb.z + h4.w*wb.w;
            }
            sm[R_HP + r*64 + lane]      = acc0;
            sm[R_HP + r*64 + 32 + lane] = acc1;
        }
        __syncthreads();
        // ==== phase 4+5: scores + softmax + weighted sum, warp-per-(r,a) ====
        {
            const int r = wid >> 1, a = wid & 1;
            float sc = -1e30f;
            if (lane < 25){
                const float4* hp = (const float4*)(sm + R_HP + r*64 + a*32);
                const float4* pr = (const float4*)(sm + R_PRE + a*7200 + r*900 + lane*36);
                const float4* w2 = (const float4*)(sm + R_W2A + a*32);
                float acc = sm[R_B2A + a];
                #pragma unroll
                for (int q = 0; q < 8; ++q){
                    float4 h4 = hp[q], p4 = pr[q], w4 = w2[q];
                    acc += fmaxf(h4.x+p4.x, 0.f)*w4.x + fmaxf(h4.y+p4.y, 0.f)*w4.y
                         + fmaxf(h4.z+p4.z, 0.f)*w4.z + fmaxf(h4.w+p4.w, 0.f)*w4.w;
                }
                sc = acc;
            }
            float m = sc;
            #pragma unroll
            for (int o = 16; o; o >>= 1) m = fmaxf(m, __shfl_xor_sync(0xffffffffu, m, o));
            float e = 0.f, o0=0.f, o1=0.f, o2=0.f, o3=0.f;
            if (lane < 25){
                e = __expf(sc - m);
                float4 mv = *(const float4*)(sm + R_MEM + a*800 + r*100 + lane*4);
                o0 = e*mv.x; o1 = e*mv.y; o2 = e*mv.z; o3 = e*mv.w;
            }
            float s = e;
            #pragma unroll
            for (int o = 16; o; o >>= 1){
                s  += __shfl_xor_sync(0xffffffffu, s,  o);
                o0 += __shfl_xor_sync(0xffffffffu, o0, o);
                o1 += __shfl_xor_sync(0xffffffffu, o1, o);
                o2 += __shfl_xor_sync(0xffffffffu, o2, o);
                o3 += __shfl_xor_sync(0xffffffffu, o3, o);
            }
            if (lane == 0){
                float inv = __fdividef(1.0f, s);
                float* ao = sm + R_AO + r*8 + a*4;
                ao[0]=o0*inv; ao[1]=o1*inv; ao[2]=o2*inv; ao[3]=o3*inv;
            }
        }
        __syncthreads();
        // ==== phase 6+7: trans MLP, warp-per-row ====
        if (wid < 8){
            const int r = wid, j = lane;
            const float* ao = sm + R_AO + r*8;
            float acc = sm[R_TB1 + j];
            #pragma unroll
            for (int d = 0; d < 8; ++d)
                acc += ao[d] * sm[R_TW1T + d*32 + j];
            sm[R_T1 + r*32 + j] = fmaxf(acc, 0.f);
            __syncwarp();
            const float4* t1v = (const float4*)(sm + R_T1 + r*32);
            const float4* wv0 = (const float4*)(sm + R_TW2T + lane*36);
            const float4* wv1 = (const float4*)(sm + R_TW2T + (lane+32)*36);
            float b0 = sm[R_TB2 + lane], b1 = sm[R_TB2 + lane + 32];
            #pragma unroll
            for (int q = 0; q < 8; ++q){
                float4 t4 = t1v[q], wa = wv0[q], wb = wv1[q];
                b0 += t4.x*wa.x + t4.y*wa.y + t4.z*wa.z + t4.w*wa.w;
                b1 += t4.x*wb.x + t4.y*wb.y + t4.z*wb.z + t4.w*wb.w;
            }
            sm[R_AV + lane*8 + r]      = b0;
            sm[R_AV + (lane+32)*8 + r] = b1;
        }
        __syncthreads();
        // ==== phase 8: language-LSTM gates (split-k, weights in regs) ====
        {
            u64 a0, a1, a2, a3;
            if (hf == 0){ u64 b = dup2(sm[R_BL + g]); a0=a1=a2=a3=b; }
            else { a0 = a1 = a2 = a3 = 0ull; }
            #pragma unroll
            for (int i = 0; i < 16; ++i){
                const float* av = sm + R_AV + (k0 + 2*i)*8;
                const float* hA = sm + R_HA + (k0 + 2*i)*8;
                const float* hL = sm + R_HL + (k0 + 2*i)*8;
                ulonglong2 v0 = *(const ulonglong2*)(av);
                ulonglong2 v1 = *(const ulonglong2*)(av + 4);
                ulonglong2 v2 = *(const ulonglong2*)(av + 8);
                ulonglong2 v3 = *(const ulonglong2*)(av + 12);
                ulonglong2 x0 = *(const ulonglong2*)(hA);
                ulonglong2 x1 = *(const ulonglong2*)(hA + 4);
                ulonglong2 x2 = *(const ulonglong2*)(hA + 8);
                ulonglong2 x3 = *(const ulonglong2*)(hA + 12);
                ulonglong2 y0 = *(const ulonglong2*)(hL);
                ulonglong2 y1 = *(const ulonglong2*)(hL + 4);
                ulonglong2 y2 = *(const ulonglong2*)(hL + 8);
                ulonglong2 y3 = *(const ulonglong2*)(hL + 12);
                u64 wa0 = dup2(rLa[i].x), wa1 = dup2(rLa[i].y);
                u64 wh0 = dup2(rLh[i].x), wh1 = dup2(rLh[i].y);
                u64 wl0 = dup2(rLl[i].x), wl1 = dup2(rLl[i].y);
                fma2(a0,wa0,v0.x); fma2(a1,wa0,v0.y); fma2(a2,wa0,v1.x); fma2(a3,wa0,v1.y);
                fma2(a0,wh0,x0.x); fma2(a1,wh0,x0.y); fma2(a2,wh0,x1.x); fma2(a3,wh0,x1.y);
                fma2(a0,wl0,y0.x); fma2(a1,wl0,y0.y); fma2(a2,wl0,y1.x); fma2(a3,wl0,y1.y);
                fma2(a0,wa1,v2.x); fma2(a1,wa1,v2.y); fma2(a2,wa1,v3.x); fma2(a3,wa1,v3.y);
                fma2(a0,wh1,x2.x); fma2(a1,wh1,x2.y); fma2(a2,wh1,x3.x); fma2(a3,wh1,x3.y);
                fma2(a0,wl1,y2.x); fma2(a1,wl1,y2.y); fma2(a2,wl1,y3.x); fma2(a3,wl1,y3.y);
            }
            float* pp = sm + R_PART + hf*2048 + g;
            float2 f;
            f = unpack2(a0); pp[0]=f.x;    pp[256]=f.y;
            f = unpack2(a1); pp[512]=f.x;  pp[768]=f.y;
            f = unpack2(a2); pp[1024]=f.x; pp[1280]=f.y;
            f = unpack2(a3); pp[1536]=f.x; pp[1792]=f.y;
        }
        __syncthreads();
        // ==== phase 9: language cell + history ====
        {
            const float* p = sm + R_PART + cr*256 + cu;
            float gi = p[0]   + p[2048];
            float gf = p[64]  + p[2112];
            float gg = p[128] + p[2176];
            float go = p[192] + p[2240];
            float c = sigf(gf)*sm[R_CL + cr*64 + cu] + sigf(gi)*ftanh(gg);
            sm[R_CL + cr*64 + cu] = c;
            float h = sigf(go)*ftanh(c);
            sm[R_HL + cu*8 + cr] = h;
            g_hist[((size_t)t*BNUM + row0 + cr)*RNNV + cu] = h;
        }
        __syncthreads();
    }
}

// ------------------------------------------------------------------
// fused output GEMM + log_softmax: 8 rows x 2001 cols, 256 threads, 3 CTAs/SM
// (R8's proven version: smem logits, coalesced float4 epilogue)
#define OST2 2008
__global__ __launch_bounds__(256, 3) void output_kernel(const float* __restrict__ fcb,
                                                        float* __restrict__ out)
{
    extern __shared__ __align__(16) float s_logit[];   // [8][OST2]
    __shared__ __align__(16) float s_h[RNNV*8];         // [k][8]
    const int tid = threadIdx.x;
    const int m0  = blockIdx.x * 8;

    {   // stage h (transpose to [k][r])
        int r = tid >> 5, k = (tid & 31) * 2;
        float2 v = *(const float2*)(g_hist + (size_t)(m0 + r)*RNNV + k);
        s_h[k*8 + r]     = v.x;
        s_h[(k+1)*8 + r] = v.y;
    }
    if (tid < 56){   // guard cols 2001..2007
        int r = tid / 7, c = V1 + tid % 7;
        s_logit[r*OST2 + c] = -1e30f;
    }
    __syncthreads();

    #pragma unroll
    for (int chunk = 0; chunk < 4; ++chunk){
        int cp = chunk*256 + tid;
        if (cp > 1000) continue;
        int c0 = cp*2;
        float bx = fcb[c0];
        float by = (c0+1 < V1) ? fcb[c0+1] : 0.f;
        u64 accA[4], accB[4];
        #pragma unroll
        for (int p = 0; p < 4; ++p){ accA[p] = dup2(bx); accB[p] = dup2(by); }
        const __half2* w = (const __half2*)g_fcwh + cp;
        #pragma unroll 8
        for (int k = 0; k < RNNV; ++k){
            float2 wf = __half22float2(w[k*1008]);
            u64 w0 = dup2(wf.x), w1 = dup2(wf.y);
            const float* hb = s_h + k*8;
            ulonglong2 hA = *(const ulonglong2*)(hb);
            ulonglong2 hB = *(const ulonglong2*)(hb + 4);
            fma2(accA[0], w0, hA.x); fma2(accA[1], w0, hA.y);
            fma2(accA[2], w0, hB.x); fma2(accA[3], w0, hB.y);
            fma2(accB[0], w1, hA.x); fma2(accB[1], w1, hA.y);
            fma2(accB[2], w1, hB.x); fma2(accB[3], w1, hB.y);
        }
        #pragma unroll
        for (int p = 0; p < 4; ++p){
            float2 f = unpack2(accA[p]);
            s_logit[(2*p)*OST2   + c0] = f.x;
            s_logit[(2*p+1)*OST2 + c0] = f.y;
        }
        if (c0 + 1 < V1){
            #pragma unroll
            for (int p = 0; p < 4; ++p){
                float2 f = unpack2(accB[p]);
                s_logit[(2*p)*OST2   + c0+1] = f.x;
                s_logit[(2*p+1)*OST2 + c0+1] = f.y;
            }
        }
    }
    __syncthreads();

    // warp-per-row: logsumexp + write
    {
        const int r = tid >> 5, lane = tid & 31;
        const float4* row = (const float4*)(s_logit + r*OST2);
        float s = 0.f;
        #pragma unroll 4
        for (int q = lane; q < 502; q += 32){
            float4 f = row[q];
            s += __expf(f.x) + __expf(f.y) + __expf(f.z) + __expf(f.w);
        }
        #pragma unroll
        for (int o = 16; o; o >>= 1)
            s += __shfl_xor_sync(0xffffffffu, s, o);
        float lse = __logf(s);

        int m = m0 + r;
        int t = m >> 10, b = m & 1023;
        float* dst = out + ((size_t)b*NT + t)*V1;
        #pragma unroll 4
        for (int q = lane; q < 501; q += 32){
            float4 f = row[q];
            int c = q*4;
            if (c + 3 < V1){
                dst[c]   = f.x - lse;
                dst[c+1] = f.y - lse;
                dst[c+2] = f.z - lse;
                dst[c+3] = f.w - lse;
            } else {
                if (c   < V1) dst[c]   = f.x - lse;
                if (c+1 < V1) dst[c+1] = f.y - lse;
                if (c+2 < V1) dst[c+2] = f.z - lse;
            }
        }
    }
}

// ------------------------------------------------------------------
extern "C" void kernel_launch(void* const* d_in, const int* in_sizes, int n_in,
                              void* d_out, int out_size)
{
    const int*   inst  = (const int*)  d_in[0];
    const float* prevc = (const float*)d_in[1];
    const float* finc  = (const float*)d_in[2];
    const float* embed = (const float*)d_in[3];
    const float* WihA  = (const float*)d_in[4];
    const float* WhhA  = (const float*)d_in[5];
    const float* bihA  = (const float*)d_in[6];
    const float* bhhA  = (const float*)d_in[7];
    const float* WihL  = (const float*)d_in[8];
    const float* WhhL  = (const float*)d_in[9];
    const float* bihL  = (const float*)d_in[10];
    const float* bhhL  = (const float*)d_in[11];
    const float* fcw   = (const float*)d_in[12];
    const float* fcb   = (const float*)d_in[13];
    const float* a1w1  = (const float*)d_in[14];
    const float* a1b1  = (const float*)d_in[15];
    const float* a1w2  = (const float*)d_in[16];
    const float* a1b2  = (const float*)d_in[17];
    const float* a2w1  = (const float*)d_in[18];
    const float* a2b1  = (const float*)d_in[19];
    const float* a2w2  = (const float*)d_in[20];
    const float* a2b2  = (const float*)d_in[21];
    const float* tw1   = (const float*)d_in[22];
    const float* tb1   = (const float*)d_in[23];
    const float* tw2   = (const float*)d_in[24];
    const float* tb2   = (const float*)d_in[25];
    float* out = (float*)d_out;

    static int smem_set = 0;
    const int logit_smem = 8 * OST2 * (int)sizeof(float);
    const int rec_smem   = R_TOTAL * (int)sizeof(float);
    if (!smem_set){
        cudaFuncSetAttribute(output_kernel,    cudaFuncAttributeMaxDynamicSharedMemorySize, logit_smem);
        cudaFuncSetAttribute(recurrent_kernel, cudaFuncAttributeMaxDynamicSharedMemorySize, rec_smem);
        smem_set = 1;
    }

    prep_weights_kernel<<<(RNNV*V1 + 255)/256, 256>>>(WihA, WhhA, WihL, WhhL, fcw);
    prep_canvas_kernel<<<(BNUM*NOBJ*HID + 255)/256, 256>>>(prevc, finc, a1w1, a1b1, a2w1, a2b1);
    xproj_kernel<<<NROW/16, 256>>>(inst, embed, bihA, bhhA);
    recurrent_kernel<<<BNUM/8, 512, rec_smem>>>(a1w1, a1w2, a1b2, a2w1, a2w2, a2b2,
                                                tw1, tb1, tw2, tb2, bihL, bhhL, prevc);
    output_kernel<<<NROW/8, 256, logit_smem>>>(fcb, out);
}

// round 12
// speedup vs baseline: 2.0382x; 2.0382x over previous
#include <cuda_runtime.h>
#include <cuda_fp16.h>
#include <math.h>

#define BNUM 1024
#define TT   48
#define NT   47
#define RNNV 64
#define GG   256
#define NOBJ 25
#define HID  32
#define V1   2001
#define NROW (NT*BNUM)

__device__ float g_xproj[(size_t)NROW*GG];
__device__ float g_hist[(size_t)NROW*RNNV];
__device__ float g_pre1[BNUM*NOBJ*HID];
__device__ float g_pre2[BNUM*NOBJ*HID];
__device__ float g_diff[BNUM*NOBJ*4];
__device__ float g_WAx[RNNV*GG];
// fp32 gate weights, 5 matrices (WAl,WAh,WLa,WLh,WLl), packed k-pairs:
// float index = m*16384 + (k>>1)*512 + g*2 + (k&1)
__device__ __align__(16) float g_WP[5*16384];
// fp16 output weights: [k][2016] (cols >= 2001 zero-padded)
__device__ __align__(16) __half g_fcwh[RNNV*2016];

typedef unsigned long long u64;

__device__ __forceinline__ u64 pack2(float lo, float hi){
    u64 r; asm("mov.b64 %0, {%1, %2};" : "=l"(r) : "f"(lo), "f"(hi)); return r;
}
__device__ __forceinline__ u64 dup2(float x){ return pack2(x, x); }
__device__ __forceinline__ void fma2(u64& acc, u64 a, u64 b){
    asm("fma.rn.f32x2 %0, %1, %2, %0;" : "+l"(acc) : "l"(a), "l"(b));
}
__device__ __forceinline__ float2 unpack2(u64 v){
    float2 f; asm("mov.b64 {%0, %1}, %2;" : "=f"(f.x), "=f"(f.y) : "l"(v)); return f;
}
__device__ __forceinline__ float sigf(float x){
    return __fdividef(1.0f, 1.0f + __expf(-x));
}
__device__ __forceinline__ float ftanh(float x){
    float e = __expf(-2.0f*x);
    return __fdividef(1.0f - e, 1.0f + e);
}

// ------------------------------------------------------------------
__global__ void prep_weights_kernel(const float* __restrict__ WihA, const float* __restrict__ WhhA,
                                    const float* __restrict__ WihL, const float* __restrict__ WhhL,
                                    const float* __restrict__ fcw)
{
    int i = blockIdx.x*blockDim.x + threadIdx.x;
    if (i < RNNV*GG){
        int k = i / GG, g = i % GG;
        g_WAx[i] = WihA[g*128 + 64 + k];
    }
    if (i < 5*RNNV*GG){
        int m = i / 16384, rem = i % 16384;
        int k = rem >> 8, g = rem & 255;
        float w;
        if      (m == 0) w = WihA[g*128 + k];
        else if (m == 1) w = WhhA[g*64 + k];
        else if (m == 2) w = WihL[g*128 + k];
        else if (m == 3) w = WihL[g*128 + 64 + k];
        else             w = WhhL[g*64 + k];
        g_WP[m*16384 + (k>>1)*512 + g*2 + (k&1)] = w;
    }
    if (i < RNNV*V1){
        int k = i / V1, v = i % V1;
        g_fcwh[k*2016 + v] = __float2half(fcw[v*RNNV + k]);
    }
    if (i < RNNV*15){
        int k = i / 15, v = V1 + i % 15;
        g_fcwh[k*2016 + v] = __float2half(0.0f);
    }
}

// ------------------------------------------------------------------
__global__ void prep_canvas_kernel(const float* __restrict__ prev, const float* __restrict__ finalc,
                                   const float* __restrict__ a1w1, const float* __restrict__ a1b1,
                                   const float* __restrict__ a2w1, const float* __restrict__ a2b1)
{
    int i = blockIdx.x*blockDim.x + threadIdx.x;
    if (i >= BNUM*NOBJ*HID) return;
    int j = i & 31, bn = i >> 5;
    float p0 = prev[bn*4+0], p1 = prev[bn*4+1], p2 = prev[bn*4+2], p3 = prev[bn*4+3];
    bool masked = (p0+p1+p2+p3) > 0.0f;
    float d0 = masked ? -1.0f : finalc[bn*4+0];
    float d1 = masked ? -1.0f : finalc[bn*4+1];
    float d2 = masked ? -1.0f : finalc[bn*4+2];
    float d3 = masked ? -1.0f : finalc[bn*4+3];
    const float* w1 = a1w1 + j*68 + 64;
    const float* w2 = a2w1 + j*68 + 64;
    g_pre1[i] = a1b1[j] + d0*w1[0] + d1*w1[1] + d2*w1[2] + d3*w1[3];
    g_pre2[i] = a2b1[j] + p0*w2[0] + p1*w2[1] + p2*w2[2] + p3*w2[3];
    if (j == 0){
        g_diff[bn*4+0] = d0; g_diff[bn*4+1] = d1;
        g_diff[bn*4+2] = d2; g_diff[bn*4+3] = d3;
    }
}

// ------------------------------------------------------------------
__global__ __launch_bounds__(256) void xproj_kernel(
    const int* __restrict__ inst, const float* __restrict__ embed,
    const float* __restrict__ b_ih, const float* __restrict__ b_hh)
{
    __shared__ __align__(16) float se[RNNV*16];  // [k][r]
    const int tid = threadIdx.x;
    const int m0 = blockIdx.x * 16;
    for (int i = tid; i < 16*RNNV; i += 256){
        int r = i >> 6, k = i & 63;
        int m = m0 + r;
        int t = m >> 10, b = m & 1023;
        int tok = inst[b*TT + t];
        se[k*16 + r] = embed[tok*RNNV + k];
    }
    __syncthreads();
    const int g = tid;
    float bias = b_ih[g] + b_hh[g];
    u64 acc[8];
    #pragma unroll
    for (int p = 0; p < 8; ++p) acc[p] = dup2(bias);
    const float* w = g_WAx + g;
    #pragma unroll 8
    for (int k = 0; k < RNNV; ++k){
        u64 wd = dup2(w[k*GG]);
        const float* e = se + k*16;
        ulonglong2 e0 = *(const ulonglong2*)(e);
        ulonglong2 e1 = *(const ulonglong2*)(e + 4);
        ulonglong2 e2 = *(const ulonglong2*)(e + 8);
        ulonglong2 e3 = *(const ulonglong2*)(e + 12);
        fma2(acc[0], wd, e0.x); fma2(acc[1], wd, e0.y);
        fma2(acc[2], wd, e1.x); fma2(acc[3], wd, e1.y);
        fma2(acc[4], wd, e2.x); fma2(acc[5], wd, e2.y);
        fma2(acc[6], wd, e3.x); fma2(acc[7], wd, e3.y);
    }
    float* xp = g_xproj + (size_t)m0*GG + g;
    #pragma unroll
    for (int p = 0; p < 8; ++p){
        float2 f = unpack2(acc[p]);
        xp[(size_t)(2*p)*GG]   = f.x;
        xp[(size_t)(2*p+1)*GG] = f.y;
    }
}

// ------------------------------------------------------------------
// recurrent: 8 rows/CTA, 512 threads, 128 CTAs  (R10's measured-best: 445 us)
// attention gate weights in REGISTERS; language gates prefetched 2-deep
#define R_HL    0        // 512  [k][8]
#define R_HA    512      // 512
#define R_AV    1024     // 512
#define R_HAR   1536     // 512  [r][64]
#define R_CA    2048     // 512  [r][u]
#define R_CL    2560     // 512
#define R_PART  3072     // 4096 [hf][r][g]
#define R_PRE   7168     // 14400 [a*7200 + r*900 + n*36 + j]
#define R_W1H   21568    // 4352  [a*2176 + j*68 + k]
#define R_TW2T  25920    // 2304  [u*36 + j]
#define R_MEM   28224    // 1600  [a][r][n*4+d]
#define R_HP    29824    // 512   [r][64]
#define R_AO    30336    // 64    [r][8]
#define R_T1    30400    // 256   [r][32]
#define R_TW1T  30656    // 256   [d][j]
#define R_W2A   30912    // 64    [a][j]
#define R_TB1   30976    // 32
#define R_TB2   31008    // 64
#define R_BL    31072    // 256
#define R_B2A   31328    // 2
#define R_TOTAL 31336

__global__ __launch_bounds__(512) void recurrent_kernel(
    const float* __restrict__ a1w1, const float* __restrict__ a1w2, const float* __restrict__ a1b2,
    const float* __restrict__ a2w1, const float* __restrict__ a2w2, const float* __restrict__ a2b2,
    const float* __restrict__ tw1,  const float* __restrict__ tb1,
    const float* __restrict__ tw2,  const float* __restrict__ tb2,
    const float* __restrict__ bihl, const float* __restrict__ bhhl,
    const float* __restrict__ prev)
{
    extern __shared__ __align__(16) float sm[];
    const int tid  = threadIdx.x;
    const int row0 = blockIdx.x * 8;

    // ------- one-time init -------
    for (int i = tid; i < 3072; i += 512) sm[i] = 0.f;   // HL HA AV HAR CA CL
    for (int i = tid; i < 12800; i += 512){
        int a = i / 6400, rem = i % 6400;
        int r = rem / 800, rem2 = rem % 800;
        int n = rem2 >> 5, j = rem2 & 31;
        const float* src = a ? g_pre2 : g_pre1;
        sm[R_PRE + a*7200 + r*900 + n*36 + j] = src[((size_t)(row0+r)*NOBJ + n)*HID + j];
    }
    for (int i = tid; i < 4096; i += 512){
        int a = i >> 11, j = (i >> 6) & 31, k = i & 63;
        sm[R_W1H + a*2176 + j*68 + k] = (a ? a2w1 : a1w1)[j*68 + k];
    }
    for (int i = tid; i < 2048; i += 512){
        int u = i >> 5, j = i & 31;
        sm[R_TW2T + u*36 + j] = tw2[u*HID + j];
    }
    for (int i = tid; i < 1600; i += 512){
        int a = i / 800, rem = i % 800, r = rem / 100, q = rem % 100;
        sm[R_MEM + i] = a ? prev[(row0+r)*100 + q] : g_diff[(row0+r)*100 + q];
    }
    if (tid < 256){ int j = tid >> 3, d = tid & 7; sm[R_TW1T + d*32 + j] = tw1[j*8 + d]; }
    if (tid < 32){
        sm[R_W2A + tid]      = a1w2[tid];
        sm[R_W2A + 32 + tid] = a2w2[tid];
        sm[R_TB1 + tid]      = tb1[tid];
    }
    if (tid < 64)  sm[R_TB2 + tid] = tb2[tid];
    if (tid < 256) sm[R_BL + tid]  = bihl[tid] + bhhl[tid];
    if (tid < 2)   sm[R_B2A + tid] = tid ? a2b2[0] : a1b2[0];
    __syncthreads();

    const int g    = tid & 255;
    const int hf   = tid >> 8;
    const int k0   = hf << 5;
    const int wid  = tid >> 5;
    const int lane = tid & 31;
    const int cu   = tid & 63, cr = tid >> 6;

    const int kp0 = k0 >> 1;
    const float2* wAl = (const float2*)(g_WP + 0*16384) + kp0*256 + g;
    const float2* wAh = (const float2*)(g_WP + 1*16384) + kp0*256 + g;
    const float2* wLa = (const float2*)(g_WP + 2*16384) + kp0*256 + g;
    const float2* wLh = (const float2*)(g_WP + 3*16384) + kp0*256 + g;
    const float2* wLl = (const float2*)(g_WP + 4*16384) + kp0*256 + g;

    // ---- preload attention gate weights into registers (t-invariant) ----
    float2 rAl[16], rAh[16];
    #pragma unroll
    for (int i = 0; i < 16; ++i){ rAl[i] = wAl[i*256]; rAh[i] = wAh[i*256]; }

    for (int t = 0; t < NT; ++t){
        // ==== phase 1: attention-LSTM gates (split-k, weights in regs) ====
        {
            float x0,x1,x2,x3,x4,x5,x6,x7;
            if (hf == 0){
                const float* xp = g_xproj + ((size_t)t*BNUM + row0)*GG + g;
                x0=xp[0];    x1=xp[GG];   x2=xp[2*GG]; x3=xp[3*GG];
                x4=xp[4*GG]; x5=xp[5*GG]; x6=xp[6*GG]; x7=xp[7*GG];
            } else { x0=x1=x2=x3=x4=x5=x6=x7=0.f; }
            u64 a0=0ull, a1=0ull, a2=0ull, a3=0ull;
            #pragma unroll
            for (int i = 0; i < 16; ++i){
                const float* hl = sm + R_HL + (k0 + 2*i)*8;
                const float* ha = sm + R_HA + (k0 + 2*i)*8;
                ulonglong2 l0 = *(const ulonglong2*)(hl);
                ulonglong2 l1 = *(const ulonglong2*)(hl + 4);
                ulonglong2 l2 = *(const ulonglong2*)(hl + 8);
                ulonglong2 l3 = *(const ulonglong2*)(hl + 12);
                ulonglong2 b0 = *(const ulonglong2*)(ha);
                ulonglong2 b1 = *(const ulonglong2*)(ha + 4);
                ulonglong2 b2 = *(const ulonglong2*)(ha + 8);
                ulonglong2 b3 = *(const ulonglong2*)(ha + 12);
                u64 wl0 = dup2(rAl[i].x), wl1 = dup2(rAl[i].y);
                u64 wh0 = dup2(rAh[i].x), wh1 = dup2(rAh[i].y);
                fma2(a0,wl0,l0.x); fma2(a1,wl0,l0.y); fma2(a2,wl0,l1.x); fma2(a3,wl0,l1.y);
                fma2(a0,wh0,b0.x); fma2(a1,wh0,b0.y); fma2(a2,wh0,b1.x); fma2(a3,wh0,b1.y);
                fma2(a0,wl1,l2.x); fma2(a1,wl1,l2.y); fma2(a2,wl1,l3.x); fma2(a3,wl1,l3.y);
                fma2(a0,wh1,b2.x); fma2(a1,wh1,b2.y); fma2(a2,wh1,b3.x); fma2(a3,wh1,b3.y);
            }
            float* pp = sm + R_PART + hf*2048 + g;
            float2 f;
            f = unpack2(a0); pp[0]=f.x+x0;    pp[256]=f.y+x1;
            f = unpack2(a1); pp[512]=f.x+x2;  pp[768]=f.y+x3;
            f = unpack2(a2); pp[1024]=f.x+x4; pp[1280]=f.y+x5;
            f = unpack2(a3); pp[1536]=f.x+x6; pp[1792]=f.y+x7;
        }
        __syncthreads();
        // ==== phase 2+3: attention cell + hp, warp-per-row ====
        if (wid < 8){
            const int r = wid;
            #pragma unroll
            for (int h = 0; h < 2; ++h){
                int u = lane + h*32;
                const float* p = sm + R_PART + r*256 + u;
                float gi = p[0]   + p[2048];
                float gf = p[64]  + p[2112];
                float gg = p[128] + p[2176];
                float go = p[192] + p[2240];
                float c = sigf(gf)*sm[R_CA + r*64 + u] + sigf(gi)*ftanh(gg);
                sm[R_CA + r*64 + u] = c;
                float hv = sigf(go)*ftanh(c);
                sm[R_HA + u*8 + r]   = hv;
                sm[R_HAR + r*64 + u] = hv;
            }
            __syncwarp();
            const float4* hv4 = (const float4*)(sm + R_HAR + r*64);
            const float4* w0v = (const float4*)(sm + R_W1H + lane*68);
            const float4* w1v = (const float4*)(sm + R_W1H + 2176 + lane*68);
            float acc0 = 0.f, acc1 = 0.f;
            #pragma unroll
            for (int q = 0; q < 16; ++q){
                float4 h4 = hv4[q], wa = w0v[q], wb = w1v[q];
                acc0 += h4.x*wa.x + h4.y*wa.y + h4.z*wa.z + h4.w*wa.w;
                acc1 += h4.x*wb.x + h4.y*wb.y + h4.z*wb.z + h4.w*wb.w;
            }
            sm[R_HP + r*64 + lane]      = acc0;
            sm[R_HP + r*64 + 32 + lane] = acc1;
        }
        __syncthreads();
        // ==== phase 4+5: scores + softmax + weighted sum, warp-per-(r,a) ====
        {
            const int r = wid >> 1, a = wid & 1;
            float sc = -1e30f;
            if (lane < 25){
                const float4* hp = (const float4*)(sm + R_HP + r*64 + a*32);
                const float4* pr = (const float4*)(sm + R_PRE + a*7200 + r*900 + lane*36);
                const float4* w2 = (const float4*)(sm + R_W2A + a*32);
                float acc = sm[R_B2A + a];
                #pragma unroll
                for (int q = 0; q < 8; ++q){
                    float4 h4 = hp[q], p4 = pr[q], w4 = w2[q];
                    acc += fmaxf(h4.x+p4.x, 0.f)*w4.x + fmaxf(h4.y+p4.y, 0.f)*w4.y
                         + fmaxf(h4.z+p4.z, 0.f)*w4.z + fmaxf(h4.w+p4.w, 0.f)*w4.w;
                }
                sc = acc;
            }
            float m = sc;
            #pragma unroll
            for (int o = 16; o; o >>= 1) m = fmaxf(m, __shfl_xor_sync(0xffffffffu, m, o));
            float e = 0.f, o0=0.f, o1=0.f, o2=0.f, o3=0.f;
            if (lane < 25){
                e = __expf(sc - m);
                float4 mv = *(const float4*)(sm + R_MEM + a*800 + r*100 + lane*4);
                o0 = e*mv.x; o1 = e*mv.y; o2 = e*mv.z; o3 = e*mv.w;
            }
            float s = e;
            #pragma unroll
            for (int o = 16; o; o >>= 1){
                s  += __shfl_xor_sync(0xffffffffu, s,  o);
                o0 += __shfl_xor_sync(0xffffffffu, o0, o);
                o1 += __shfl_xor_sync(0xffffffffu, o1, o);
                o2 += __shfl_xor_sync(0xffffffffu, o2, o);
                o3 += __shfl_xor_sync(0xffffffffu, o3, o);
            }
            if (lane == 0){
                float inv = __fdividef(1.0f, s);
                float* ao = sm + R_AO + r*8 + a*4;
                ao[0]=o0*inv; ao[1]=o1*inv; ao[2]=o2*inv; ao[3]=o3*inv;
            }
        }
        __syncthreads();
        // ==== phase 6+7: trans MLP, warp-per-row ====
        if (wid < 8){
            const int r = wid, j = lane;
            const float* ao = sm + R_AO + r*8;
            float acc = sm[R_TB1 + j];
            #pragma unroll
            for (int d = 0; d < 8; ++d)
                acc += ao[d] * sm[R_TW1T + d*32 + j];
            sm[R_T1 + r*32 + j] = fmaxf(acc, 0.f);
            __syncwarp();
            const float4* t1v = (const float4*)(sm + R_T1 + r*32);
            const float4* wv0 = (const float4*)(sm + R_TW2T + lane*36);
            const float4* wv1 = (const float4*)(sm + R_TW2T + (lane+32)*36);
            float b0 = sm[R_TB2 + lane], b1 = sm[R_TB2 + lane + 32];
            #pragma unroll
            for (int q = 0; q < 8; ++q){
                float4 t4 = t1v[q], wa = wv0[q], wb = wv1[q];
                b0 += t4.x*wa.x + t4.y*wa.y + t4.z*wa.z + t4.w*wa.w;
                b1 += t4.x*wb.x + t4.y*wb.y + t4.z*wb.z + t4.w*wb.w;
            }
            sm[R_AV + lane*8 + r]      = b0;
            sm[R_AV + (lane+32)*8 + r] = b1;
        }
        __syncthreads();
        // ==== phase 8: language-LSTM gates (split-k, 2-deep weight prefetch) ====
        {
            u64 a0, a1, a2, a3;
            if (hf == 0){ u64 b = dup2(sm[R_BL + g]); a0=a1=a2=a3=b; }
            else { a0 = a1 = a2 = a3 = 0ull; }
            float2 pa0 = wLa[0],   pH0 = wLh[0],   pl0 = wLl[0];
            float2 pa1 = wLa[256], pH1 = wLh[256], pl1 = wLl[256];
            #pragma unroll
            for (int i = 0; i < 16; ++i){
                float2 wa = pa0, wh = pH0, wl = pl0;
                pa0 = pa1; pH0 = pH1; pl0 = pl1;
                if (i < 14){
                    pa1 = wLa[(i+2)*256]; pH1 = wLh[(i+2)*256]; pl1 = wLl[(i+2)*256];
                }
                const float* av = sm + R_AV + (k0 + 2*i)*8;
                const float* hA = sm + R_HA + (k0 + 2*i)*8;
                const float* hL = sm + R_HL + (k0 + 2*i)*8;
                ulonglong2 v0 = *(const ulonglong2*)(av);
                ulonglong2 v1 = *(const ulonglong2*)(av + 4);
                ulonglong2 v2 = *(const ulonglong2*)(av + 8);
                ulonglong2 v3 = *(const ulonglong2*)(av + 12);
                ulonglong2 x0 = *(const ulonglong2*)(hA);
                ulonglong2 x1 = *(const ulonglong2*)(hA + 4);
                ulonglong2 x2 = *(const ulonglong2*)(hA + 8);
                ulonglong2 x3 = *(const ulonglong2*)(hA + 12);
                ulonglong2 y0 = *(const ulonglong2*)(hL);
                ulonglong2 y1 = *(const ulonglong2*)(hL + 4);
                ulonglong2 y2 = *(const ulonglong2*)(hL + 8);
                ulonglong2 y3 = *(const ulonglong2*)(hL + 12);
                u64 wa0 = dup2(wa.x), wa1 = dup2(wa.y);
                u64 wh0 = dup2(wh.x), wh1 = dup2(wh.y);
                u64 wl0 = dup2(wl.x), wl1 = dup2(wl.y);
                fma2(a0,wa0,v0.x); fma2(a1,wa0,v0.y); fma2(a2,wa0,v1.x); fma2(a3,wa0,v1.y);
                fma2(a0,wh0,x0.x); fma2(a1,wh0,x0.y); fma2(a2,wh0,x1.x); fma2(a3,wh0,x1.y);
                fma2(a0,wl0,y0.x); fma2(a1,wl0,y0.y); fma2(a2,wl0,y1.x); fma2(a3,wl0,y1.y);
                fma2(a0,wa1,v2.x); fma2(a1,wa1,v2.y); fma2(a2,wa1,v3.x); fma2(a3,wa1,v3.y);
                fma2(a0,wh1,x2.x); fma2(a1,wh1,x2.y); fma2(a2,wh1,x3.x); fma2(a3,wh1,x3.y);
                fma2(a0,wl1,y2.x); fma2(a1,wl1,y2.y); fma2(a2,wl1,y3.x); fma2(a3,wl1,y3.y);
            }
            float* pp = sm + R_PART + hf*2048 + g;
            float2 f;
            f = unpack2(a0); pp[0]=f.x;    pp[256]=f.y;
            f = unpack2(a1); pp[512]=f.x;  pp[768]=f.y;
            f = unpack2(a2); pp[1024]=f.x; pp[1280]=f.y;
            f = unpack2(a3); pp[1536]=f.x; pp[1792]=f.y;
        }
        __syncthreads();
        // ==== phase 9: language cell + history ====
        {
            const float* p = sm + R_PART + cr*256 + cu;
            float gi = p[0]   + p[2048];
            float gf = p[64]  + p[2112];
            float gg = p[128] + p[2176];
            float go = p[192] + p[2240];
            float c = sigf(gf)*sm[R_CL + cr*64 + cu] + sigf(gi)*ftanh(gg);
            sm[R_CL + cr*64 + cu] = c;
            float h = sigf(go)*ftanh(c);
            sm[R_HL + cu*8 + cr] = h;
            g_hist[((size_t)t*BNUM + row0 + cr)*RNNV + cu] = h;
        }
        __syncthreads();
    }
}

// ------------------------------------------------------------------
// fused output GEMM + log_softmax: 8 rows x 2001 cols, 256 threads, 3 CTAs/SM
// (R8's measured-best output kernel)
#define OST2 2008
__global__ __launch_bounds__(256, 3) void output_kernel(const float* __restrict__ fcb,
                                                        float* __restrict__ out)
{
    extern __shared__ __align__(16) float s_logit[];   // [8][OST2]
    __shared__ __align__(16) float s_h[RNNV*8];         // [k][8]
    const int tid = threadIdx.x;
    const int m0  = blockIdx.x * 8;

    {   // stage h (transpose to [k][r])
        int r = tid >> 5, k = (tid & 31) * 2;
        float2 v = *(const float2*)(g_hist + (size_t)(m0 + r)*RNNV + k);
        s_h[k*8 + r]     = v.x;
        s_h[(k+1)*8 + r] = v.y;
    }
    if (tid < 56){   // guard cols 2001..2007
        int r = tid / 7, c = V1 + tid % 7;
        s_logit[r*OST2 + c] = -1e30f;
    }
    __syncthreads();

    #pragma unroll
    for (int chunk = 0; chunk < 4; ++chunk){
        int cp = chunk*256 + tid;
        if (cp > 1000) continue;
        int c0 = cp*2;
        float bx = fcb[c0];
        float by = (c0+1 < V1) ? fcb[c0+1] : 0.f;
        u64 accA[4], accB[4];
        #pragma unroll
        for (int p = 0; p < 4; ++p){ accA[p] = dup2(bx); accB[p] = dup2(by); }
        const __half2* w = (const __half2*)g_fcwh + cp;
        #pragma unroll 8
        for (int k = 0; k < RNNV; ++k){
            float2 wf = __half22float2(w[k*1008]);
            u64 w0 = dup2(wf.x), w1 = dup2(wf.y);
            const float* hb = s_h + k*8;
            ulonglong2 hA = *(const ulonglong2*)(hb);
            ulonglong2 hB = *(const ulonglong2*)(hb + 4);
            fma2(accA[0], w0, hA.x); fma2(accA[1], w0, hA.y);
            fma2(accA[2], w0, hB.x); fma2(accA[3], w0, hB.y);
            fma2(accB[0], w1, hA.x); fma2(accB[1], w1, hA.y);
            fma2(accB[2], w1, hB.x); fma2(accB[3], w1, hB.y);
        }
        #pragma unroll
        for (int p = 0; p < 4; ++p){
            float2 f = unpack2(accA[p]);
            s_logit[(2*p)*OST2   + c0] = f.x;
            s_logit[(2*p+1)*OST2 + c0] = f.y;
        }
        if (c0 + 1 < V1){
            #pragma unroll
            for (int p = 0; p < 4; ++p){
                float2 f = unpack2(accB[p]);
                s_logit[(2*p)*OST2   + c0+1] = f.x;
                s_logit[(2*p+1)*OST2 + c0+1] = f.y;
            }
        }
    }
    __syncthreads();

    // warp-per-row: logsumexp + write
    {
        const int r = tid >> 5, lane = tid & 31;
        const float4* row = (const float4*)(s_logit + r*OST2);
        float s = 0.f;
        #pragma unroll 4
        for (int q = lane; q < 502; q += 32){
            float4 f = row[q];
            s += __expf(f.x) + __expf(f.y) + __expf(f.z) + __expf(f.w);
        }
        #pragma unroll
        for (int o = 16; o; o >>= 1)
            s += __shfl_xor_sync(0xffffffffu, s, o);
        float lse = __logf(s);

        int m = m0 + r;
        int t = m >> 10, b = m & 1023;
        float* dst = out + ((size_t)b*NT + t)*V1;
        #pragma unroll 4
        for (int q = lane; q < 501; q += 32){
            float4 f = row[q];
            int c = q*4;
            if (c + 3 < V1){
                dst[c]   = f.x - lse;
                dst[c+1] = f.y - lse;
                dst[c+2] = f.z - lse;
                dst[c+3] = f.w - lse;
            } else {
                if (c   < V1) dst[c]   = f.x - lse;
                if (c+1 < V1) dst[c+1] = f.y - lse;
                if (c+2 < V1) dst[c+2] = f.z - lse;
            }
        }
    }
}

// ------------------------------------------------------------------
extern "C" void kernel_launch(void* const* d_in, const int* in_sizes, int n_in,
                              void* d_out, int out_size)
{
    const int*   inst  = (const int*)  d_in[0];
    const float* prevc = (const float*)d_in[1];
    const float* finc  = (const float*)d_in[2];
    const float* embed = (const float*)d_in[3];
    const float* WihA  = (const float*)d_in[4];
    const float* WhhA  = (const float*)d_in[5];
    const float* bihA  = (const float*)d_in[6];
    const float* bhhA  = (const float*)d_in[7];
    const float* WihL  = (const float*)d_in[8];
    const float* WhhL  = (const float*)d_in[9];
    const float* bihL  = (const float*)d_in[10];
    const float* bhhL  = (const float*)d_in[11];
    const float* fcw   = (const float*)d_in[12];
    const float* fcb   = (const float*)d_in[13];
    const float* a1w1  = (const float*)d_in[14];
    const float* a1b1  = (const float*)d_in[15];
    const float* a1w2  = (const float*)d_in[16];
    const float* a1b2  = (const float*)d_in[17];
    const float* a2w1  = (const float*)d_in[18];
    const float* a2b1  = (const float*)d_in[19];
    const float* a2w2  = (const float*)d_in[20];
    const float* a2b2  = (const float*)d_in[21];
    const float* tw1   = (const float*)d_in[22];
    const float* tb1   = (const float*)d_in[23];
    const float* tw2   = (const float*)d_in[24];
    const float* tb2   = (const float*)d_in[25];
    float* out = (float*)d_out;

    static int smem_set = 0;
    const int logit_smem = 8 * OST2 * (int)sizeof(float);
    const int rec_smem   = R_TOTAL * (int)sizeof(float);
    if (!smem_set){
        cudaFuncSetAttribute(output_kernel,    cudaFuncAttributeMaxDynamicSharedMemorySize, logit_smem);
        cudaFuncSetAttribute(recurrent_kernel, cudaFuncAttributeMaxDynamicSharedMemorySize, rec_smem);
        smem_set = 1;
    }

    prep_weights_kernel<<<(RNNV*V1 + 255)/256, 256>>>(WihA, WhhA, WihL, WhhL, fcw);
    prep_canvas_kernel<<<(BNUM*NOBJ*HID + 255)/256, 256>>>(prevc, finc, a1w1, a1b1, a2w1, a2b1);
    xproj_kernel<<<NROW/16, 256>>>(inst, embed, bihA, bhhA);
    recurrent_kernel<<<BNUM/8, 512, rec_smem>>>(a1w1, a1w2, a1b2, a2w1, a2w2, a2b2,
                                                tw1, tb1, tw2, tb2, bihL, bhhL, prevc);
    output_kernel<<<NROW/8, 256, logit_smem>>>(fcb, out);
}

// round 13
// speedup vs baseline: 2.0933x; 1.0270x over previous
#include <cuda_runtime.h>
#include <cuda_fp16.h>
#include <math.h>

#define BNUM 1024
#define TT   48
#define NT   47
#define RNNV 64
#define GG   256
#define NOBJ 25
#define HID  32
#define V1   2001
#define NROW (NT*BNUM)

__device__ float g_xproj[(size_t)NROW*GG];
__device__ float g_hist[(size_t)NROW*RNNV];
__device__ float g_pre1[BNUM*NOBJ*HID];
__device__ float g_pre2[BNUM*NOBJ*HID];
__device__ float g_diff[BNUM*NOBJ*4];
__device__ float g_WAx[RNNV*GG];
// fp32 gate weights, 5 matrices (WAl,WAh,WLa,WLh,WLl), packed k-pairs:
// float index = m*16384 + (k>>1)*512 + g*2 + (k&1)
__device__ __align__(16) float g_WP[5*16384];
// fp16 output weights: [k][2048] (cols >= 2001 zero-padded; stride 4096B)
__device__ __align__(16) __half g_fcwh[RNNV*2048];

typedef unsigned long long u64;

__device__ __forceinline__ u64 pack2(float lo, float hi){
    u64 r; asm("mov.b64 %0, {%1, %2};" : "=l"(r) : "f"(lo), "f"(hi)); return r;
}
__device__ __forceinline__ u64 dup2(float x){ return pack2(x, x); }
__device__ __forceinline__ void fma2(u64& acc, u64 a, u64 b){
    asm("fma.rn.f32x2 %0, %1, %2, %0;" : "+l"(acc) : "l"(a), "l"(b));
}
__device__ __forceinline__ float2 unpack2(u64 v){
    float2 f; asm("mov.b64 {%0, %1}, %2;" : "=f"(f.x), "=f"(f.y) : "l"(v)); return f;
}
__device__ __forceinline__ float sigf(float x){
    return __fdividef(1.0f, 1.0f + __expf(-x));
}
__device__ __forceinline__ float ftanh(float x){
    float e = __expf(-2.0f*x);
    return __fdividef(1.0f - e, 1.0f + e);
}

// ------------------------------------------------------------------
__global__ void prep_weights_kernel(const float* __restrict__ WihA, const float* __restrict__ WhhA,
                                    const float* __restrict__ WihL, const float* __restrict__ WhhL,
                                    const float* __restrict__ fcw)
{
    int i = blockIdx.x*blockDim.x + threadIdx.x;
    if (i < RNNV*GG){
        int k = i / GG, g = i % GG;
        g_WAx[i] = WihA[g*128 + 64 + k];
    }
    if (i < 5*RNNV*GG){
        int m = i / 16384, rem = i % 16384;
        int k = rem >> 8, g = rem & 255;
        float w;
        if      (m == 0) w = WihA[g*128 + k];
        else if (m == 1) w = WhhA[g*64 + k];
        else if (m == 2) w = WihL[g*128 + k];
        else if (m == 3) w = WihL[g*128 + 64 + k];
        else             w = WhhL[g*64 + k];
        g_WP[m*16384 + (k>>1)*512 + g*2 + (k&1)] = w;
    }
    if (i < RNNV*2048){
        int k = i >> 11, v = i & 2047;
        g_fcwh[i] = __float2half(v < V1 ? fcw[v*RNNV + k] : 0.0f);
    }
}

// ------------------------------------------------------------------
__global__ void prep_canvas_kernel(const float* __restrict__ prev, const float* __restrict__ finalc,
                                   const float* __restrict__ a1w1, const float* __restrict__ a1b1,
                                   const float* __restrict__ a2w1, const float* __restrict__ a2b1)
{
    int i = blockIdx.x*blockDim.x + threadIdx.x;
    if (i >= BNUM*NOBJ*HID) return;
    int j = i & 31, bn = i >> 5;
    float p0 = prev[bn*4+0], p1 = prev[bn*4+1], p2 = prev[bn*4+2], p3 = prev[bn*4+3];
    bool masked = (p0+p1+p2+p3) > 0.0f;
    float d0 = masked ? -1.0f : finalc[bn*4+0];
    float d1 = masked ? -1.0f : finalc[bn*4+1];
    float d2 = masked ? -1.0f : finalc[bn*4+2];
    float d3 = masked ? -1.0f : finalc[bn*4+3];
    const float* w1 = a1w1 + j*68 + 64;
    const float* w2 = a2w1 + j*68 + 64;
    g_pre1[i] = a1b1[j] + d0*w1[0] + d1*w1[1] + d2*w1[2] + d3*w1[3];
    g_pre2[i] = a2b1[j] + p0*w2[0] + p1*w2[1] + p2*w2[2] + p3*w2[3];
    if (j == 0){
        g_diff[bn*4+0] = d0; g_diff[bn*4+1] = d1;
        g_diff[bn*4+2] = d2; g_diff[bn*4+3] = d3;
    }
}

// ------------------------------------------------------------------
__global__ __launch_bounds__(256) void xproj_kernel(
    const int* __restrict__ inst, const float* __restrict__ embed,
    const float* __restrict__ b_ih, const float* __restrict__ b_hh)
{
    __shared__ __align__(16) float se[RNNV*16];  // [k][r]
    const int tid = threadIdx.x;
    const int m0 = blockIdx.x * 16;
    for (int i = tid; i < 16*RNNV; i += 256){
        int r = i >> 6, k = i & 63;
        int m = m0 + r;
        int t = m >> 10, b = m & 1023;
        int tok = inst[b*TT + t];
        se[k*16 + r] = embed[tok*RNNV + k];
    }
    __syncthreads();
    const int g = tid;
    float bias = b_ih[g] + b_hh[g];
    u64 acc[8];
    #pragma unroll
    for (int p = 0; p < 8; ++p) acc[p] = dup2(bias);
    const float* w = g_WAx + g;
    #pragma unroll 8
    for (int k = 0; k < RNNV; ++k){
        u64 wd = dup2(w[k*GG]);
        const float* e = se + k*16;
        ulonglong2 e0 = *(const ulonglong2*)(e);
        ulonglong2 e1 = *(const ulonglong2*)(e + 4);
        ulonglong2 e2 = *(const ulonglong2*)(e + 8);
        ulonglong2 e3 = *(const ulonglong2*)(e + 12);
        fma2(acc[0], wd, e0.x); fma2(acc[1], wd, e0.y);
        fma2(acc[2], wd, e1.x); fma2(acc[3], wd, e1.y);
        fma2(acc[4], wd, e2.x); fma2(acc[5], wd, e2.y);
        fma2(acc[6], wd, e3.x); fma2(acc[7], wd, e3.y);
    }
    float* xp = g_xproj + (size_t)m0*GG + g;
    #pragma unroll
    for (int p = 0; p < 8; ++p){
        float2 f = unpack2(acc[p]);
        xp[(size_t)(2*p)*GG]   = f.x;
        xp[(size_t)(2*p+1)*GG] = f.y;
    }
}

// ------------------------------------------------------------------
// recurrent: 8 rows/CTA, 512 threads, 128 CTAs  (R12 measured-best: 442 us)
#define R_HL    0        // 512  [k][8]
#define R_HA    512      // 512
#define R_AV    1024     // 512
#define R_HAR   1536     // 512  [r][64]
#define R_CA    2048     // 512  [r][u]
#define R_CL    2560     // 512
#define R_PART  3072     // 4096 [hf][r][g]
#define R_PRE   7168     // 14400 [a*7200 + r*900 + n*36 + j]
#define R_W1H   21568    // 4352  [a*2176 + j*68 + k]
#define R_TW2T  25920    // 2304  [u*36 + j]
#define R_MEM   28224    // 1600  [a][r][n*4+d]
#define R_HP    29824    // 512   [r][64]
#define R_AO    30336    // 64    [r][8]
#define R_T1    30400    // 256   [r][32]
#define R_TW1T  30656    // 256   [d][j]
#define R_W2A   30912    // 64    [a][j]
#define R_TB1   30976    // 32
#define R_TB2   31008    // 64
#define R_BL    31072    // 256
#define R_B2A   31328    // 2
#define R_TOTAL 31336

__global__ __launch_bounds__(512) void recurrent_kernel(
    const float* __restrict__ a1w1, const float* __restrict__ a1w2, const float* __restrict__ a1b2,
    const float* __restrict__ a2w1, const float* __restrict__ a2w2, const float* __restrict__ a2b2,
    const float* __restrict__ tw1,  const float* __restrict__ tb1,
    const float* __restrict__ tw2,  const float* __restrict__ tb2,
    const float* __restrict__ bihl, const float* __restrict__ bhhl,
    const float* __restrict__ prev)
{
    extern __shared__ __align__(16) float sm[];
    const int tid  = threadIdx.x;
    const int row0 = blockIdx.x * 8;

    for (int i = tid; i < 3072; i += 512) sm[i] = 0.f;
    for (int i = tid; i < 12800; i += 512){
        int a = i / 6400, rem = i % 6400;
        int r = rem / 800, rem2 = rem % 800;
        int n = rem2 >> 5, j = rem2 & 31;
        const float* src = a ? g_pre2 : g_pre1;
        sm[R_PRE + a*7200 + r*900 + n*36 + j] = src[((size_t)(row0+r)*NOBJ + n)*HID + j];
    }
    for (int i = tid; i < 4096; i += 512){
        int a = i >> 11, j = (i >> 6) & 31, k = i & 63;
        sm[R_W1H + a*2176 + j*68 + k] = (a ? a2w1 : a1w1)[j*68 + k];
    }
    for (int i = tid; i < 2048; i += 512){
        int u = i >> 5, j = i & 31;
        sm[R_TW2T + u*36 + j] = tw2[u*HID + j];
    }
    for (int i = tid; i < 1600; i += 512){
        int a = i / 800, rem = i % 800, r = rem / 100, q = rem % 100;
        sm[R_MEM + i] = a ? prev[(row0+r)*100 + q] : g_diff[(row0+r)*100 + q];
    }
    if (tid < 256){ int j = tid >> 3, d = tid & 7; sm[R_TW1T + d*32 + j] = tw1[j*8 + d]; }
    if (tid < 32){
        sm[R_W2A + tid]      = a1w2[tid];
        sm[R_W2A + 32 + tid] = a2w2[tid];
        sm[R_TB1 + tid]      = tb1[tid];
    }
    if (tid < 64)  sm[R_TB2 + tid] = tb2[tid];
    if (tid < 256) sm[R_BL + tid]  = bihl[tid] + bhhl[tid];
    if (tid < 2)   sm[R_B2A + tid] = tid ? a2b2[0] : a1b2[0];
    __syncthreads();

    const int g    = tid & 255;
    const int hf   = tid >> 8;
    const int k0   = hf << 5;
    const int wid  = tid >> 5;
    const int lane = tid & 31;
    const int cu   = tid & 63, cr = tid >> 6;

    const int kp0 = k0 >> 1;
    const float2* wAl = (const float2*)(g_WP + 0*16384) + kp0*256 + g;
    const float2* wAh = (const float2*)(g_WP + 1*16384) + kp0*256 + g;
    const float2* wLa = (const float2*)(g_WP + 2*16384) + kp0*256 + g;
    const float2* wLh = (const float2*)(g_WP + 3*16384) + kp0*256 + g;
    const float2* wLl = (const float2*)(g_WP + 4*16384) + kp0*256 + g;

    float2 rAl[16], rAh[16];
    #pragma unroll
    for (int i = 0; i < 16; ++i){ rAl[i] = wAl[i*256]; rAh[i] = wAh[i*256]; }

    for (int t = 0; t < NT; ++t){
        // ==== phase 1: attention-LSTM gates ====
        {
            float x0,x1,x2,x3,x4,x5,x6,x7;
            if (hf == 0){
                const float* xp = g_xproj + ((size_t)t*BNUM + row0)*GG + g;
                x0=xp[0];    x1=xp[GG];   x2=xp[2*GG]; x3=xp[3*GG];
                x4=xp[4*GG]; x5=xp[5*GG]; x6=xp[6*GG]; x7=xp[7*GG];
            } else { x0=x1=x2=x3=x4=x5=x6=x7=0.f; }
            u64 a0=0ull, a1=0ull, a2=0ull, a3=0ull;
            #pragma unroll
            for (int i = 0; i < 16; ++i){
                const float* hl = sm + R_HL + (k0 + 2*i)*8;
                const float* ha = sm + R_HA + (k0 + 2*i)*8;
                ulonglong2 l0 = *(const ulonglong2*)(hl);
                ulonglong2 l1 = *(const ulonglong2*)(hl + 4);
                ulonglong2 l2 = *(const ulonglong2*)(hl + 8);
                ulonglong2 l3 = *(const ulonglong2*)(hl + 12);
                ulonglong2 b0 = *(const ulonglong2*)(ha);
                ulonglong2 b1 = *(const ulonglong2*)(ha + 4);
                ulonglong2 b2 = *(const ulonglong2*)(ha + 8);
                ulonglong2 b3 = *(const ulonglong2*)(ha + 12);
                u64 wl0 = dup2(rAl[i].x), wl1 = dup2(rAl[i].y);
                u64 wh0 = dup2(rAh[i].x), wh1 = dup2(rAh[i].y);
                fma2(a0,wl0,l0.x); fma2(a1,wl0,l0.y); fma2(a2,wl0,l1.x); fma2(a3,wl0,l1.y);
                fma2(a0,wh0,b0.x); fma2(a1,wh0,b0.y); fma2(a2,wh0,b1.x); fma2(a3,wh0,b1.y);
                fma2(a0,wl1,l2.x); fma2(a1,wl1,l2.y); fma2(a2,wl1,l3.x); fma2(a3,wl1,l3.y);
                fma2(a0,wh1,b2.x); fma2(a1,wh1,b2.y); fma2(a2,wh1,b3.x); fma2(a3,wh1,b3.y);
            }
            float* pp = sm + R_PART + hf*2048 + g;
            float2 f;
            f = unpack2(a0); pp[0]=f.x+x0;    pp[256]=f.y+x1;
            f = unpack2(a1); pp[512]=f.x+x2;  pp[768]=f.y+x3;
            f = unpack2(a2); pp[1024]=f.x+x4; pp[1280]=f.y+x5;
            f = unpack2(a3); pp[1536]=f.x+x6; pp[1792]=f.y+x7;
        }
        __syncthreads();
        // ==== phase 2+3: attention cell + hp ====
        if (wid < 8){
            const int r = wid;
            #pragma unroll
            for (int h = 0; h < 2; ++h){
                int u = lane + h*32;
                const float* p = sm + R_PART + r*256 + u;
                float gi = p[0]   + p[2048];
                float gf = p[64]  + p[2112];
                float gg = p[128] + p[2176];
                float go = p[192] + p[2240];
                float c = sigf(gf)*sm[R_CA + r*64 + u] + sigf(gi)*ftanh(gg);
                sm[R_CA + r*64 + u] = c;
                float hv = sigf(go)*ftanh(c);
                sm[R_HA + u*8 + r]   = hv;
                sm[R_HAR + r*64 + u] = hv;
            }
            __syncwarp();
            const float4* hv4 = (const float4*)(sm + R_HAR + r*64);
            const float4* w0v = (const float4*)(sm + R_W1H + lane*68);
            const float4* w1v = (const float4*)(sm + R_W1H + 2176 + lane*68);
            float acc0 = 0.f, acc1 = 0.f;
            #pragma unroll
            for (int q = 0; q < 16; ++q){
                float4 h4 = hv4[q], wa = w0v[q], wb = w1v[q];
                acc0 += h4.x*wa.x + h4.y*wa.y + h4.z*wa.z + h4.w*wa.w;
                acc1 += h4.x*wb.x + h4.y*wb.y + h4.z*wb.z + h4.w*wb.w;
            }
            sm[R_HP + r*64 + lane]      = acc0;
            sm[R_HP + r*64 + 32 + lane] = acc1;
        }
        __syncthreads();
        // ==== phase 4+5: scores + softmax + weighted sum ====
        {
            const int r = wid >> 1, a = wid & 1;
            float sc = -1e30f;
            if (lane < 25){
                const float4* hp = (const float4*)(sm + R_HP + r*64 + a*32);
                const float4* pr = (const float4*)(sm + R_PRE + a*7200 + r*900 + lane*36);
                const float4* w2 = (const float4*)(sm + R_W2A + a*32);
                float acc = sm[R_B2A + a];
                #pragma unroll
                for (int q = 0; q < 8; ++q){
                    float4 h4 = hp[q], p4 = pr[q], w4 = w2[q];
                    acc += fmaxf(h4.x+p4.x, 0.f)*w4.x + fmaxf(h4.y+p4.y, 0.f)*w4.y
                         + fmaxf(h4.z+p4.z, 0.f)*w4.z + fmaxf(h4.w+p4.w, 0.f)*w4.w;
                }
                sc = acc;
            }
            float m = sc;
            #pragma unroll
            for (int o = 16; o; o >>= 1) m = fmaxf(m, __shfl_xor_sync(0xffffffffu, m, o));
            float e = 0.f, o0=0.f, o1=0.f, o2=0.f, o3=0.f;
            if (lane < 25){
                e = __expf(sc - m);
                float4 mv = *(const float4*)(sm + R_MEM + a*800 + r*100 + lane*4);
                o0 = e*mv.x; o1 = e*mv.y; o2 = e*mv.z; o3 = e*mv.w;
            }
            float s = e;
            #pragma unroll
            for (int o = 16; o; o >>= 1){
                s  += __shfl_xor_sync(0xffffffffu, s,  o);
                o0 += __shfl_xor_sync(0xffffffffu, o0, o);
                o1 += __shfl_xor_sync(0xffffffffu, o1, o);
                o2 += __shfl_xor_sync(0xffffffffu, o2, o);
                o3 += __shfl_xor_sync(0xffffffffu, o3, o);
            }
            if (lane == 0){
                float inv = __fdividef(1.0f, s);
                float* ao = sm + R_AO + r*8 + a*4;
                ao[0]=o0*inv; ao[1]=o1*inv; ao[2]=o2*inv; ao[3]=o3*inv;
            }
        }
        __syncthreads();
        // ==== phase 6+7: trans MLP ====
        if (wid < 8){
            const int r = wid, j = lane;
            const float* ao = sm + R_AO + r*8;
            float acc = sm[R_TB1 + j];
            #pragma unroll
            for (int d = 0; d < 8; ++d)
                acc += ao[d] * sm[R_TW1T + d*32 + j];
            sm[R_T1 + r*32 + j] = fmaxf(acc, 0.f);
            __syncwarp();
            const float4* t1v = (const float4*)(sm + R_T1 + r*32);
            const float4* wv0 = (const float4*)(sm + R_TW2T + lane*36);
            const float4* wv1 = (const float4*)(sm + R_TW2T + (lane+32)*36);
            float b0 = sm[R_TB2 + lane], b1 = sm[R_TB2 + lane + 32];
            #pragma unroll
            for (int q = 0; q < 8; ++q){
                float4 t4 = t1v[q], wa = wv0[q], wb = wv1[q];
                b0 += t4.x*wa.x + t4.y*wa.y + t4.z*wa.z + t4.w*wa.w;
                b1 += t4.x*wb.x + t4.y*wb.y + t4.z*wb.z + t4.w*wb.w;
            }
            sm[R_AV + lane*8 + r]      = b0;
            sm[R_AV + (lane+32)*8 + r] = b1;
        }
        __syncthreads();
        // ==== phase 8: language-LSTM gates (2-deep weight prefetch) ====
        {
            u64 a0, a1, a2, a3;
            if (hf == 0){ u64 b = dup2(sm[R_BL + g]); a0=a1=a2=a3=b; }
            else { a0 = a1 = a2 = a3 = 0ull; }
            float2 pa0 = wLa[0],   pH0 = wLh[0],   pl0 = wLl[0];
            float2 pa1 = wLa[256], pH1 = wLh[256], pl1 = wLl[256];
            #pragma unroll
            for (int i = 0; i < 16; ++i){
                float2 wa = pa0, wh = pH0, wl = pl0;
                pa0 = pa1; pH0 = pH1; pl0 = pl1;
                if (i < 14){
                    pa1 = wLa[(i+2)*256]; pH1 = wLh[(i+2)*256]; pl1 = wLl[(i+2)*256];
                }
                const float* av = sm + R_AV + (k0 + 2*i)*8;
                const float* hA = sm + R_HA + (k0 + 2*i)*8;
                const float* hL = sm + R_HL + (k0 + 2*i)*8;
                ulonglong2 v0 = *(const ulonglong2*)(av);
                ulonglong2 v1 = *(const ulonglong2*)(av + 4);
                ulonglong2 v2 = *(const ulonglong2*)(av + 8);
                ulonglong2 v3 = *(const ulonglong2*)(av + 12);
                ulonglong2 x0 = *(const ulonglong2*)(hA);
                ulonglong2 x1 = *(const ulonglong2*)(hA + 4);
                ulonglong2 x2 = *(const ulonglong2*)(hA + 8);
                ulonglong2 x3 = *(const ulonglong2*)(hA + 12);
                ulonglong2 y0 = *(const ulonglong2*)(hL);
                ulonglong2 y1 = *(const ulonglong2*)(hL + 4);
                ulonglong2 y2 = *(const ulonglong2*)(hL + 8);
                ulonglong2 y3 = *(const ulonglong2*)(hL + 12);
                u64 wa0 = dup2(wa.x), wa1 = dup2(wa.y);
                u64 wh0 = dup2(wh.x), wh1 = dup2(wh.y);
                u64 wl0 = dup2(wl.x), wl1 = dup2(wl.y);
                fma2(a0,wa0,v0.x); fma2(a1,wa0,v0.y); fma2(a2,wa0,v1.x); fma2(a3,wa0,v1.y);
                fma2(a0,wh0,x0.x); fma2(a1,wh0,x0.y); fma2(a2,wh0,x1.x); fma2(a3,wh0,x1.y);
                fma2(a0,wl0,y0.x); fma2(a1,wl0,y0.y); fma2(a2,wl0,y1.x); fma2(a3,wl0,y1.y);
                fma2(a0,wa1,v2.x); fma2(a1,wa1,v2.y); fma2(a2,wa1,v3.x); fma2(a3,wa1,v3.y);
                fma2(a0,wh1,x2.x); fma2(a1,wh1,x2.y); fma2(a2,wh1,x3.x); fma2(a3,wh1,x3.y);
                fma2(a0,wl1,y2.x); fma2(a1,wl1,y2.y); fma2(a2,wl1,y3.x); fma2(a3,wl1,y3.y);
            }
            float* pp = sm + R_PART + hf*2048 + g;
            float2 f;
            f = unpack2(a0); pp[0]=f.x;    pp[256]=f.y;
            f = unpack2(a1); pp[512]=f.x;  pp[768]=f.y;
            f = unpack2(a2); pp[1024]=f.x; pp[1280]=f.y;
            f = unpack2(a3); pp[1536]=f.x; pp[1792]=f.y;
        }
        __syncthreads();
        // ==== phase 9: language cell + history ====
        {
            const float* p = sm + R_PART + cr*256 + cu;
            float gi = p[0]   + p[2048];
            float gf = p[64]  + p[2112];
            float gg = p[128] + p[2176];
            float go = p[192] + p[2240];
            float c = sigf(gf)*sm[R_CL + cr*64 + cu] + sigf(gi)*ftanh(gg);
            sm[R_CL + cr*64 + cu] = c;
            float h = sigf(go)*ftanh(c);
            sm[R_HL + cu*8 + cr] = h;
            g_hist[((size_t)t*BNUM + row0 + cr)*RNNV + cu] = h;
        }
        __syncthreads();
    }
}

// ------------------------------------------------------------------
// fused output GEMM + log_softmax: 8 rows x 2001 cols, 256 threads, 3 CTAs/SM
// 4 cols/thread (LDG.64 weights, stride 2048), STS.128 logit stores
#define OST2 2008
__global__ __launch_bounds__(256, 3) void output_kernel(const float* __restrict__ fcb,
                                                        float* __restrict__ out)
{
    extern __shared__ __align__(16) float s_logit[];   // [8][OST2]
    __shared__ __align__(16) float s_h[RNNV*8];         // [k][8]
    const int tid = threadIdx.x;
    const int m0  = blockIdx.x * 8;

    {   // stage h (transpose to [k][r])
        int r = tid >> 5, k = (tid & 31) * 2;
        float2 v = *(const float2*)(g_hist + (size_t)(m0 + r)*RNNV + k);
        s_h[k*8 + r]     = v.x;
        s_h[(k+1)*8 + r] = v.y;
    }
    __syncthreads();

    #pragma unroll
    for (int chunk = 0; chunk < 2; ++chunk){
        int cp = chunk*256 + tid;     // group of 4 columns
        int c0 = cp*4;
        float b0 = (c0   < V1) ? fcb[c0]   : 0.f;
        float b1 = (c0+1 < V1) ? fcb[c0+1] : 0.f;
        float b2 = (c0+2 < V1) ? fcb[c0+2] : 0.f;
        float b3 = (c0+3 < V1) ? fcb[c0+3] : 0.f;
        u64 A0[4], A1[4], A2[4], A3[4];
        #pragma unroll
        for (int p = 0; p < 4; ++p){
            A0[p]=dup2(b0); A1[p]=dup2(b1); A2[p]=dup2(b2); A3[p]=dup2(b3);
        }
        const __half* wbase = g_fcwh + c0;
        #pragma unroll 4
        for (int k = 0; k < RNNV; ++k){
            uint2 wu = *(const uint2*)(wbase + ((size_t)k << 11));
            float2 w01 = __half22float2(*(const __half2*)&wu.x);
            float2 w23 = __half22float2(*(const __half2*)&wu.y);
            u64 w0 = dup2(w01.x), w1 = dup2(w01.y);
            u64 w2 = dup2(w23.x), w3 = dup2(w23.y);
            const float* hb = s_h + k*8;
            ulonglong2 hA = *(const ulonglong2*)(hb);
            ulonglong2 hB = *(const ulonglong2*)(hb + 4);
            fma2(A0[0], w0, hA.x); fma2(A0[1], w0, hA.y); fma2(A0[2], w0, hB.x); fma2(A0[3], w0, hB.y);
            fma2(A1[0], w1, hA.x); fma2(A1[1], w1, hA.y); fma2(A1[2], w1, hB.x); fma2(A1[3], w1, hB.y);
            fma2(A2[0], w2, hA.x); fma2(A2[1], w2, hA.y); fma2(A2[2], w2, hB.x); fma2(A2[3], w2, hB.y);
            fma2(A3[0], w3, hA.x); fma2(A3[1], w3, hA.y); fma2(A3[2], w3, hB.x); fma2(A3[3], w3, hB.y);
        }
        if (c0 < OST2){   // cols >= 2008 never stored (zero weights, unused)
            #pragma unroll
            for (int p = 0; p < 4; ++p){
                float2 f0 = unpack2(A0[p]);
                float2 f1 = unpack2(A1[p]);
                float2 f2 = unpack2(A2[p]);
                float2 f3 = unpack2(A3[p]);
                *(float4*)(s_logit + (2*p)*OST2   + c0) = make_float4(f0.x, f1.x, f2.x, f3.x);
                *(float4*)(s_logit + (2*p+1)*OST2 + c0) = make_float4(f0.y, f1.y, f2.y, f3.y);
            }
        }
    }
    __syncthreads();
    if (tid < 56){   // neutralize padded cols 2001..2007 before lse
        int r = tid / 7, c = V1 + tid % 7;
        s_logit[r*OST2 + c] = -1e30f;
    }
    __syncthreads();

    // warp-per-row: logsumexp + write
    {
        const int r = tid >> 5, lane = tid & 31;
        const float4* row = (const float4*)(s_logit + r*OST2);
        float s = 0.f;
        #pragma unroll 4
        for (int q = lane; q < 502; q += 32){
            float4 f = row[q];
            s += __expf(f.x) + __expf(f.y) + __expf(f.z) + __expf(f.w);
        }
        #pragma unroll
        for (int o = 16; o; o >>= 1)
            s += __shfl_xor_sync(0xffffffffu, s, o);
        float lse = __logf(s);

        int m = m0 + r;
        int t = m >> 10, b = m & 1023;
        float* dst = out + ((size_t)b*NT + t)*V1;
        #pragma unroll 4
        for (int q = lane; q < 501; q += 32){
            float4 f = row[q];
            int c = q*4;
            if (c + 3 < V1){
                dst[c]   = f.x - lse;
                dst[c+1] = f.y - lse;
                dst[c+2] = f.z - lse;
                dst[c+3] = f.w - lse;
            } else {
                if (c   < V1) dst[c]   = f.x - lse;
                if (c+1 < V1) dst[c+1] = f.y - lse;
                if (c+2 < V1) dst[c+2] = f.z - lse;
            }
        }
    }
}

// ------------------------------------------------------------------
extern "C" void kernel_launch(void* const* d_in, const int* in_sizes, int n_in,
                              void* d_out, int out_size)
{
    const int*   inst  = (const int*)  d_in[0];
    const float* prevc = (const float*)d_in[1];
    const float* finc  = (const float*)d_in[2];
    const float* embed = (const float*)d_in[3];
    const float* WihA  = (const float*)d_in[4];
    const float* WhhA  = (const float*)d_in[5];
    const float* bihA  = (const float*)d_in[6];
    const float* bhhA  = (const float*)d_in[7];
    const float* WihL  = (const float*)d_in[8];
    const float* WhhL  = (const float*)d_in[9];
    const float* bihL  = (const float*)d_in[10];
    const float* bhhL  = (const float*)d_in[11];
    const float* fcw   = (const float*)d_in[12];
    const float* fcb   = (const float*)d_in[13];
    const float* a1w1  = (const float*)d_in[14];
    const float* a1b1  = (const float*)d_in[15];
    const float* a1w2  = (const float*)d_in[16];
    const float* a1b2  = (const float*)d_in[17];
    const float* a2w1  = (const float*)d_in[18];
    const float* a2b1  = (const float*)d_in[19];
    const float* a2w2  = (const float*)d_in[20];
    const float* a2b2  = (const float*)d_in[21];
    const float* tw1   = (const float*)d_in[22];
    const float* tb1   = (const float*)d_in[23];
    const float* tw2   = (const float*)d_in[24];
    const float* tb2   = (const float*)d_in[25];
    float* out = (float*)d_out;

    static int smem_set = 0;
    const int logit_smem = 8 * OST2 * (int)sizeof(float);
    const int rec_smem   = R_TOTAL * (int)sizeof(float);
    if (!smem_set){
        cudaFuncSetAttribute(output_kernel,    cudaFuncAttributeMaxDynamicSharedMemorySize, logit_smem);
        cudaFuncSetAttribute(recurrent_kernel, cudaFuncAttributeMaxDynamicSharedMemorySize, rec_smem);
        smem_set = 1;
    }

    prep_weights_kernel<<<(RNNV*2048 + 255)/256, 256>>>(WihA, WhhA, WihL, WhhL, fcw);
    prep_canvas_kernel<<<(BNUM*NOBJ*HID + 255)/256, 256>>>(prevc, finc, a1w1, a1b1, a2w1, a2b1);
    xproj_kernel<<<NROW/16, 256>>>(inst, embed, bihA, bhhA);
    recurrent_kernel<<<BNUM/8, 512, rec_smem>>>(a1w1, a1w2, a1b2, a2w1, a2w2, a2b2,
                                                tw1, tb1, tw2, tb2, bihL, bhhL, prevc);
    output_kernel<<<NROW/8, 256, logit_smem>>>(fcb, out);
}